// round 1
// baseline (speedup 1.0000x reference)
#include <cuda_runtime.h>

#define TT 17
#define TM 16
#define DN 128
#define HH 256
#define PP 128
#define EE 32
#define MM 128

// scratch (no allocations allowed)
__device__ float g_enc[TT*DN*PP];   // encoder output, 17 timesteps
__device__ float g_A  [TT*DN*MM];   // h @ Wm[:P]
__device__ float g_agg[TT*DN*MM];   // max-aggregated messages
__device__ float g_hg [TT*DN*PP];   // GNN layer output
__device__ float g_NA [TT*DN*PP];   // hg @ Wc1[0:P]
__device__ float g_CA [TT*DN*PP];   // hg @ Wc1[P:2P]
__device__ float g_Bp [DN*DN*MM];   // e_enc @ Wm[P:] + bm   (only live pairs)
__device__ float g_E1 [DN*DN*PP];   // e_enc @ Wc1[2P:] + bc1 (only live pairs)
__device__ int   g_nbr[DN*DN];
__device__ int   g_cnt[DN];

// ---------------------------------------------------------------- init logits
__global__ void k_init(float* out){
    int idx = blockIdx.x*blockDim.x + threadIdx.x;   // 512*128 threads, 4 floats each
    ((float4*)out)[idx] = make_float4(-1e9f,-1e9f,-1e9f,-1e9f);
}

// ---------------------------------------------------------------- neighbor lists
__global__ void k_nbr(const float* __restrict__ w){
    int i = threadIdx.x;
    int c = 0;
    for(int j=0;j<DN;j++){
        if(w[i*DN+j] > 0.f || j==i) g_nbr[i*DN + c++] = j;
    }
    g_cnt[i] = c;
}

// ---------------------------------------------------------------- node encoder
// enc[s,d,p] = relu( sum_h x[s,h,d]*Wn[h,p] + bn[p] )
__global__ void k_enc(const float* __restrict__ x, const float* __restrict__ Wn,
                      const float* __restrict__ bn){
    int d = blockIdx.x, s = blockIdx.y, p = threadIdx.x;
    __shared__ float xr[HH];
    xr[p]       = x[(s*HH + p      )*DN + d];
    xr[p + 128] = x[(s*HH + p + 128)*DN + d];
    __syncthreads();
    float acc = bn[p];
    #pragma unroll 8
    for(int h=0;h<HH;h++) acc = fmaf(xr[h], Wn[h*PP + p], acc);
    g_enc[(s*DN + d)*PP + p] = fmaxf(acc, 0.f);
}

// ---------------------------------------------------------------- A = enc @ Wm[:P]
__global__ void k_A(const float* __restrict__ Wm){
    int d = blockIdx.x, s = blockIdx.y, m = threadIdx.x;
    __shared__ float hr[PP];
    hr[m] = g_enc[(s*DN + d)*PP + m];
    __syncthreads();
    float acc = 0.f;
    #pragma unroll 8
    for(int k=0;k<PP;k++) acc = fmaf(hr[k], Wm[k*MM + m], acc);
    g_A[(s*DN + d)*MM + m] = acc;
}

// ---------------------------------------------------------------- per-edge encodings
// For live pairs: v = relu(w*We + be);  Bp = v@Wm[P:] + bm;  E1 = v@Wc1[2P:] + bc1
__global__ void k_edge(const float* __restrict__ w,  const float* __restrict__ We,
                       const float* __restrict__ be, const float* __restrict__ Wm,
                       const float* __restrict__ bm, const float* __restrict__ Wc1,
                       const float* __restrict__ bc1){
    int i = blockIdx.x, tid = threadIdx.x;
    __shared__ float v[EE];
    int cnt = g_cnt[i];
    for(int k=0;k<cnt;k++){
        int j = g_nbr[i*DN + k];
        if(tid < EE){
            float wij = w[i*DN + j];
            v[tid] = fmaxf(fmaf(wij, We[tid], be[tid]), 0.f);
        }
        __syncthreads();
        float b  = bm[tid];
        float e1 = bc1[tid];
        #pragma unroll
        for(int e=0;e<EE;e++){
            float ve = v[e];
            b  = fmaf(ve, Wm [(PP   + e)*MM + tid], b );
            e1 = fmaf(ve, Wc1[(2*PP + e)*PP + tid], e1);
        }
        int off = (i*DN + j)*MM + tid;
        g_Bp[off] = b;
        g_E1[off] = e1;
        __syncthreads();   // protect v before next iteration rewrites it
    }
}

// ---------------------------------------------------------------- message aggregation
// agg[s,i,m] = max_{j in N(i)} max(0, A[s,j,m] + Bp[i,j,m])
__global__ void k_agg(){
    int i = blockIdx.x, m = threadIdx.x;
    float acc[TT];
    #pragma unroll
    for(int s=0;s<TT;s++) acc[s] = 0.f;   // relu floor: max(acc0=0, v) == max over relu(v)
    int cnt = g_cnt[i];
    for(int k=0;k<cnt;k++){
        int j = g_nbr[i*DN + k];
        float b = g_Bp[(i*DN + j)*MM + m];
        int base = j*MM + m;
        #pragma unroll
        for(int s=0;s<TT;s++){
            acc[s] = fmaxf(acc[s], g_A[s*DN*MM + base] + b);
        }
    }
    #pragma unroll
    for(int s=0;s<TT;s++) g_agg[(s*DN + i)*MM + m] = acc[s];
}

// ---------------------------------------------------------------- update + gate
__global__ void k_upd(const float* __restrict__ Wu, const float* __restrict__ bu,
                      const float* __restrict__ Wg, const float* __restrict__ bg){
    int d = blockIdx.x, s = blockIdx.y, p = threadIdx.x;
    __shared__ float cat[PP + MM];
    cat[p]       = g_enc[(s*DN + d)*PP + p];
    cat[p + PP]  = g_agg[(s*DN + d)*MM + p];
    __syncthreads();
    float u = bu[p], g = bg[p];
    #pragma unroll 8
    for(int k=0;k<PP+MM;k++){
        float c = cat[k];
        u = fmaf(c, Wu[k*PP + p], u);
        g = fmaf(c, Wg[k*PP + p], g);
    }
    float up = fmaxf(u, 0.f);
    float gg = 1.f / (1.f + __expf(-g));
    g_hg[(s*DN + d)*PP + p] = gg*up + (1.f - gg)*cat[p];
}

// ---------------------------------------------------------------- NA / CA projections
__global__ void k_nc(const float* __restrict__ Wc1){
    int d = blockIdx.x, s = blockIdx.y, m = threadIdx.x;
    __shared__ float hr[PP];
    hr[m] = g_hg[(s*DN + d)*PP + m];
    __syncthreads();
    float a1 = 0.f, a2 = 0.f;
    #pragma unroll 8
    for(int k=0;k<PP;k++){
        float h = hr[k];
        a1 = fmaf(h, Wc1[ k       *PP + m], a1);
        a2 = fmaf(h, Wc1[(PP + k) *PP + m], a2);
    }
    g_NA[(s*DN + d)*PP + m] = a1;
    g_CA[(s*DN + d)*PP + m] = a2;
}

// ---------------------------------------------------------------- logits (sparse pairs)
// logits[t,i,j] = sum_m relu(NA[t+1,i,m]+CA[t,j,m]+E1[i,j,m]) * Wc2[m] + bc2
__global__ void k_logits(const float* __restrict__ Wc2, const float* __restrict__ bc2,
                         float* __restrict__ out){
    int i = blockIdx.x, t = blockIdx.y;
    int lane = threadIdx.x & 31, w = threadIdx.x >> 5;
    float4 na = *(const float4*)&g_NA[((t+1)*DN + i)*PP + lane*4];
    float4 wc = *(const float4*)&Wc2[lane*4];
    float bc2v = bc2[0];
    int cnt = g_cnt[i];
    for(int k=w; k<cnt; k+=4){
        int j = g_nbr[i*DN + k];
        float4 ca = *(const float4*)&g_CA[(t*DN + j)*PP + lane*4];
        float4 e1 = *(const float4*)&g_E1[(i*DN + j)*PP + lane*4];
        float s;
        s  = fmaxf(na.x + ca.x + e1.x, 0.f) * wc.x;
        s += fmaxf(na.y + ca.y + e1.y, 0.f) * wc.y;
        s += fmaxf(na.z + ca.z + e1.z, 0.f) * wc.z;
        s += fmaxf(na.w + ca.w + e1.w, 0.f) * wc.w;
        #pragma unroll
        for(int off=16; off; off>>=1) s += __shfl_xor_sync(0xffffffffu, s, off);
        if(lane == 0) out[t*DN*DN + i*DN + j] = s + bc2v;
    }
}

// ---------------------------------------------------------------- dist head
__global__ void k_dist(const float* __restrict__ Wd1, const float* __restrict__ bd1,
                       const float* __restrict__ Wd2, const float* __restrict__ bd2,
                       float* __restrict__ out){
    int d = blockIdx.x, t = blockIdx.y, p = threadIdx.x;
    __shared__ float df[2*PP];
    __shared__ float red[PP];
    df[p]      = g_hg[( t     *DN + d)*PP + p];
    df[p + PP] = g_hg[((t+1)*DN + d)*PP + p];
    __syncthreads();
    float acc = bd1[p];
    #pragma unroll 8
    for(int k=0;k<2*PP;k++) acc = fmaf(df[k], Wd1[k*PP + p], acc);
    red[p] = fmaxf(acc, 0.f) * Wd2[p];
    __syncthreads();
    if(p < 64) red[p] += red[p + 64];
    __syncthreads();
    if(p < 32){
        float s = red[p] + red[p + 32];
        #pragma unroll
        for(int off=16; off; off>>=1) s += __shfl_xor_sync(0xffffffffu, s, off);
        if(p == 0) out[TM*DN*DN + t*DN + d] = s + bd2[0];
    }
}

// ---------------------------------------------------------------- host launcher
extern "C" void kernel_launch(void* const* d_in, const int* in_sizes, int n_in,
                              void* d_out, int out_size){
    // expected input sizes in metadata order; negative semantics: optional entries
    struct Exp { int sz; bool opt; };
    static const Exp exp_[23] = {
        {557056,false}, // x
        {16384 ,false}, // edge_w
        {128   ,true }, // batch
        {1     ,true }, // no_graphs
        {2     ,true }, // time_i
        {32768 ,false},{128,false},          // Wn, bn
        {32    ,false},{32 ,false},          // We, be
        {20480 ,false},{128,false},          // Wm, bm
        {32768 ,false},{128,false},          // Wu, bu
        {32768 ,false},{128,false},          // Wg, bg
        {36864 ,false},{128,false},          // Wc1, bc1
        {128   ,false},{1  ,false},          // Wc2, bc2
        {32768 ,false},{128,false},          // Wd1, bd1
        {128   ,false},{1  ,false},          // Wd2, bd2
    };
    const void* ptr[23] = {};
    int pos = 0;
    for(int e=0;e<23;e++){
        if(pos < n_in && in_sizes[pos] == exp_[e].sz){ ptr[e] = d_in[pos]; pos++; }
        else if(exp_[e].opt){ ptr[e] = nullptr; }
        else if(pos < n_in){ ptr[e] = d_in[pos]; pos++; }
    }
    const float* x    = (const float*)ptr[0];
    const float* ew   = (const float*)ptr[1];
    const float* Wn   = (const float*)ptr[5];
    const float* bn   = (const float*)ptr[6];
    const float* We   = (const float*)ptr[7];
    const float* be   = (const float*)ptr[8];
    const float* Wm   = (const float*)ptr[9];
    const float* bm   = (const float*)ptr[10];
    const float* Wu   = (const float*)ptr[11];
    const float* bu   = (const float*)ptr[12];
    const float* Wg   = (const float*)ptr[13];
    const float* bg   = (const float*)ptr[14];
    const float* Wc1  = (const float*)ptr[15];
    const float* bc1  = (const float*)ptr[16];
    const float* Wc2  = (const float*)ptr[17];
    const float* bc2  = (const float*)ptr[18];
    const float* Wd1  = (const float*)ptr[19];
    const float* bd1  = (const float*)ptr[20];
    const float* Wd2  = (const float*)ptr[21];
    const float* bd2  = (const float*)ptr[22];
    float* out = (float*)d_out;

    k_init  <<<512, 128>>>(out);                 // fill logits region with -1e9
    k_nbr   <<<1, 128>>>(ew);
    k_enc   <<<dim3(DN, TT), 128>>>(x, Wn, bn);
    k_edge  <<<DN, 128>>>(ew, We, be, Wm, bm, Wc1, bc1);
    k_A     <<<dim3(DN, TT), 128>>>(Wm);
    k_agg   <<<DN, 128>>>();
    k_upd   <<<dim3(DN, TT), 128>>>(Wu, bu, Wg, bg);
    k_nc    <<<dim3(DN, TT), 128>>>(Wc1);
    k_logits<<<dim3(DN, TM), 128>>>(Wc2, bc2, out);
    k_dist  <<<dim3(DN, TM), 128>>>(Wd1, bd1, Wd2, bd2, out);
}